// round 16
// baseline (speedup 1.0000x reference)
#include <cuda_runtime.h>
#include <cuda_fp16.h>
#include <math.h>

#define NMAX 100000
#define EMAX 3200000
#define BMAX 512
#define H 32
#define FIN 64
#define KNTN 32
#define BUCKET 64

typedef unsigned long long ull;

// ---- static scratch (no allocation) ----
__device__ __align__(16) __half g_nbh[2][2 * NMAX * H];   // fp16 feature ping-pong
__device__ __align__(16) __half g_rh[2 * NMAX * H];       // fp16 root term r = h@Wr + bl
__device__ __align__(16) float  g_rep[2 * NMAX * H];      // final rep (fp32)
__device__ int   g_cur[2 * NMAX];                         // degree / bucket cursor
__device__ int   g_csr[2 * NMAX * BUCKET + 1024];         // interleaved CSR (+pad for prefetch)
__device__ float g_gm[2][BMAX * H];
__device__ int   g_gmcnt[2][BMAX];
__device__ float g_pool[2][BMAX * H];
__device__ float g_ctx[2][BMAX * H];

// ---- f32x2 packed helpers ----
__device__ __forceinline__ ull pack2(float a, float b) {
    ull r; asm("mov.b64 %0, {%1,%2};" : "=l"(r) : "f"(a), "f"(b)); return r;
}
__device__ __forceinline__ void unpack2(ull v, float& a, float& b) {
    asm("mov.b64 {%0,%1}, %2;" : "=f"(a), "=f"(b) : "l"(v));
}
__device__ __forceinline__ ull fma2(ull a, ull b, ull c) {
    ull d; asm("fma.rn.f32x2 %0, %1, %2, %3;" : "=l"(d) : "l"(a), "l"(b), "l"(c));
    return d;
}
__device__ __forceinline__ void red_add_v4(float* p, float4 v) {
    asm volatile("red.global.add.v4.f32 [%0], {%1,%2,%3,%4};"
                 :: "l"(p), "f"(v.x), "f"(v.y), "f"(v.z), "f"(v.w) : "memory");
}

// interleaved CSR slot for node u, entry t
__device__ __forceinline__ int csr_slot(int u, int t) {
    return (u & ~7) * BUCKET + t * 8 + (u & 7);
}

// ---------------- init (split 3-way so fill is launch #4 for ncu) ----------------
__global__ void k_init_cur(int n2) {
    int i = blockIdx.x * blockDim.x + threadIdx.x;
    if (i < n2) g_cur[i] = 0;
}
__global__ void k_init_gm(int B) {
    int i = blockIdx.x * blockDim.x + threadIdx.x;
    if (i < B * H) {
        g_gm[0][i] = 0.f; g_gm[1][i] = 0.f;
        g_pool[0][i] = 0.f; g_pool[1][i] = 0.f;
    }
}
__global__ void k_init_cnt(int B) {
    int i = blockIdx.x * blockDim.x + threadIdx.x;
    if (i < B) { g_gmcnt[0][i] = 0; g_gmcnt[1][i] = 0; }
}

// ---------------- CSR fill: 1 edge/thread (proven 84us) ----------------
__global__ void k_fill(const int* __restrict__ ei, const int* __restrict__ ej,
                       int N, int E) {
    int idx = blockIdx.x * blockDim.x + threadIdx.x;
    if (idx >= 2 * E) return;
    int side = idx >= E;
    int e = idx - side * E;
    const int* el = side ? ej : ei;
    int s = el[e];
    int d = el[E + e];
    int u = side * N + d;
    int pos = atomicAdd(&g_cur[u], 1);
    if (pos < BUCKET) g_csr[csr_slot(u, pos)] = side * N + s;
}

// ---------------- xw: y = (x @ W_gcn) * dinv -> nbh[0] (fp16, prescaled) ----------------
__global__ void k_xw(const float* __restrict__ xi, const float* __restrict__ xj,
                     const float* __restrict__ W, int N) {
    __shared__ float2 sW2[32 * H];
    for (int i = threadIdx.x; i < 32 * H; i += blockDim.x)
        sW2[i] = make_float2(W[i], W[i + 32 * H]);
    __syncthreads();
    int u = blockIdx.x * (blockDim.x >> 5) + (threadIdx.x >> 5);
    int lane = threadIdx.x & 31;
    if (u >= 2 * N) return;
    int side = u >= N;
    int v = u - side * N;
    const float* x = side ? xj : xi;
    float xa = x[v * FIN + lane];
    float xb = x[v * FIN + 32 + lane];
    ull acc2 = pack2(0.f, 0.f);
    const ull* w2 = reinterpret_cast<const ull*>(sW2);
#pragma unroll
    for (int k = 0; k < 32; k++) {
        float ak = __shfl_sync(0xffffffffu, xa, k);
        float bk = __shfl_sync(0xffffffffu, xb, k);
        acc2 = fma2(pack2(ak, bk), w2[k * H + lane], acc2);
    }
    float lo, hi;
    unpack2(acc2, lo, hi);
    float dinv = rsqrtf((float)g_cur[u] + 1.f);
    g_nbh[0][u * H + lane] = __float2half((lo + hi) * dinv);
}

// ---- grp gather, unroll 2, software-pipelined index prefetch ----
__device__ __forceinline__ void grp_gather(__half2* acc, const float4* rows,
                                           int u, int deg, int sub) {
    const int* idx = g_csr + (u & ~7) * BUCKET + (u & 7);
    __half2 a1[4];
#pragma unroll
    for (int j = 0; j < 4; j++) { acc[j] = __float2half2_rn(0.f); a1[j] = acc[j]; }
    int s0 = idx[0];
    int s1 = idx[8];
    int t = 0;
    for (; t + 2 <= deg; t += 2) {
        float4 v0 = rows[s0 * 4 + sub];
        float4 v1 = rows[s1 * 4 + sub];
        s0 = idx[(t + 2) * 8];
        s1 = idx[(t + 2) * 8 + 8];
        const __half2* p0 = reinterpret_cast<const __half2*>(&v0);
        const __half2* p1 = reinterpret_cast<const __half2*>(&v1);
#pragma unroll
        for (int j = 0; j < 4; j++) acc[j] = __hadd2(acc[j], p0[j]);
#pragma unroll
        for (int j = 0; j < 4; j++) a1[j] = __hadd2(a1[j], p1[j]);
    }
    if (t < deg) {
        float4 v = rows[s0 * 4 + sub];
        const __half2* p = reinterpret_cast<const __half2*>(&v);
#pragma unroll
        for (int j = 0; j < 4; j++) acc[j] = __hadd2(acc[j], p[j]);
    }
#pragma unroll
    for (int j = 0; j < 4; j++) acc[j] = __hadd2(acc[j], a1[j]);
}

// ---------------- fused GCN gather + finalize: nbh0(prescaled) -> nbh1 ----------------
__global__ void k_gcn(const float* __restrict__ bg, int N) {
    int gw = blockIdx.x * (blockDim.x >> 5) + (threadIdx.x >> 5);
    int lane = threadIdx.x & 31;
    int grp = lane >> 2, sub = lane & 3;
    int u = gw * 8 + grp;
    if (u >= 2 * N) return;
    int deg = min(g_cur[u], BUCKET);
    const float4* y4 = reinterpret_cast<const float4*>(g_nbh[0]);
    __half2 acc[4];
    grp_gather(acc, y4, u, deg, sub);
    float4 v = y4[u * 4 + sub];
    const __half2* p = reinterpret_cast<const __half2*>(&v);
    float dinv = rsqrtf((float)g_cur[u] + 1.f);
    const float4* b4 = reinterpret_cast<const float4*>(bg);
    float4 b0 = b4[sub * 2], b1 = b4[sub * 2 + 1];
    float bv[8] = {b0.x, b0.y, b0.z, b0.w, b1.x, b1.y, b1.z, b1.w};
    __half2 out[4];
#pragma unroll
    for (int j = 0; j < 4; j++) {
        float2 s = __half22float2(acc[j]);
        float2 f = __half22float2(p[j]);
        float a = fmaxf((s.x + f.x) * dinv + bv[2 * j], 0.f);
        float b = fmaxf((s.y + f.y) * dinv + bv[2 * j + 1], 0.f);
        out[j] = __floats2half2_rn(a, b);
    }
    reinterpret_cast<float4*>(g_nbh[1])[u * 4 + sub] = *reinterpret_cast<float4*>(out);
}

// ---------------- dense lin: z = h@Wl -> nbh[si^1] (fp16), r = h@Wr + bl -> g_rh ----
// grp layout, fused-GEMV instruction structure (4 LDS.128 + 8 fma2 + 1 shfl per k)
__global__ void k_lin(int si,
                      const float* __restrict__ Wl, const float* __restrict__ bl,
                      const float* __restrict__ Wr, int N) {
    __shared__ float2 sW[H * H];   // {Wl[k][d], Wr[k][d]}
    for (int i = threadIdx.x; i < H * H; i += blockDim.x)
        sW[i] = make_float2(Wl[i], Wr[i]);
    __syncthreads();
    int gw = blockIdx.x * (blockDim.x >> 5) + (threadIdx.x >> 5);
    int lane = threadIdx.x & 31;
    int grp = lane >> 2, sub = lane & 3;
    int n2 = 2 * N;
    int u = gw * 8 + grp;
    bool alive = u < n2;
    int uc = alive ? u : (n2 - 1);
    // own h row -> hv[8]
    float hv[8];
    {
        float4 v = reinterpret_cast<const float4*>(g_nbh[si])[uc * 4 + sub];
        const __half2* p = reinterpret_cast<const __half2*>(&v);
#pragma unroll
        for (int j = 0; j < 4; j++) {
            float2 f = __half22float2(p[j]);
            hv[2 * j] = f.x; hv[2 * j + 1] = f.y;
        }
    }
    int d0 = sub * 8;
    // accumulators hold (z_d, r_d); r starts at bias
    ull acc2[8];
    {
        const float4* bl4 = reinterpret_cast<const float4*>(bl + d0);
        float4 bb0 = bl4[0], bb1 = bl4[1];
        float bv[8] = {bb0.x, bb0.y, bb0.z, bb0.w, bb1.x, bb1.y, bb1.z, bb1.w};
#pragma unroll
        for (int j = 0; j < 8; j++) acc2[j] = pack2(0.f, bv[j]);
    }
    int lanebase = lane & ~3;
    for (int k0 = 0; k0 < 32; k0 += 8) {
        int srcl = lanebase | (k0 >> 3);
#pragma unroll
        for (int i = 0; i < 8; i++) {
            int k = k0 + i;
            float hk = __shfl_sync(0xffffffffu, hv[i], srcl);
            ull hk2 = pack2(hk, hk);
            const float4* w4 = reinterpret_cast<const float4*>(sW + k * H + d0);
            float4 wa = w4[0], wb = w4[1], wc = w4[2], wd = w4[3];
            const ull* pa = reinterpret_cast<const ull*>(&wa);
            const ull* pb = reinterpret_cast<const ull*>(&wb);
            const ull* pc = reinterpret_cast<const ull*>(&wc);
            const ull* pd = reinterpret_cast<const ull*>(&wd);
            acc2[0] = fma2(hk2, pa[0], acc2[0]);
            acc2[1] = fma2(hk2, pa[1], acc2[1]);
            acc2[2] = fma2(hk2, pb[0], acc2[2]);
            acc2[3] = fma2(hk2, pb[1], acc2[3]);
            acc2[4] = fma2(hk2, pc[0], acc2[4]);
            acc2[5] = fma2(hk2, pc[1], acc2[5]);
            acc2[6] = fma2(hk2, pd[0], acc2[6]);
            acc2[7] = fma2(hk2, pd[1], acc2[7]);
        }
    }
    if (!alive) return;
    float z[8], r[8];
#pragma unroll
    for (int j = 0; j < 8; j++) unpack2(acc2[j], z[j], r[j]);
    __half2 zo[4], ro[4];
#pragma unroll
    for (int j = 0; j < 4; j++) {
        zo[j] = __floats2half2_rn(z[2 * j], z[2 * j + 1]);
        ro[j] = __floats2half2_rn(r[2 * j], r[2 * j + 1]);
    }
    reinterpret_cast<float4*>(g_nbh[si ^ 1])[u * 4 + sub] = *reinterpret_cast<float4*>(zo);
    reinterpret_cast<float4*>(g_rh)[u * 4 + sub]         = *reinterpret_cast<float4*>(ro);
}

// ---------------- pure SAGE gather: out = relu(sum(z)/cnt + r) ----------------
// reads z rows from nbh[si], r from g_rh; writes h -> nbh[si^1] or rep(+pool)
__global__ void k_pure(int si, int N, int do_pool,
                       const int* __restrict__ bi, const int* __restrict__ bj) {
    int gw = blockIdx.x * (blockDim.x >> 5) + (threadIdx.x >> 5);
    int lane = threadIdx.x & 31;
    int grp = lane >> 2, sub = lane & 3;
    int u = gw * 8 + grp;
    if (u >= 2 * N) return;
    int deg = min(g_cur[u], BUCKET);
    const float4* z4 = reinterpret_cast<const float4*>(g_nbh[si]);
    __half2 acc[4];
    grp_gather(acc, z4, u, deg, sub);
    float invc = 1.f / fmaxf((float)deg, 1.f);
    // own r row
    float4 rv = reinterpret_cast<const float4*>(g_rh)[u * 4 + sub];
    const __half2* rp2 = reinterpret_cast<const __half2*>(&rv);
    float a[8];
#pragma unroll
    for (int j = 0; j < 4; j++) {
        float2 s = __half22float2(acc[j]);
        float2 f = __half22float2(rp2[j]);
        a[2 * j]     = fmaxf(s.x * invc + f.x, 0.f);
        a[2 * j + 1] = fmaxf(s.y * invc + f.y, 0.f);
    }
    int d0 = sub * 8;
    if (do_pool) {
        float4* op = reinterpret_cast<float4*>(g_rep + u * H + d0);
        op[0] = make_float4(a[0], a[1], a[2], a[3]);
        op[1] = make_float4(a[4], a[5], a[6], a[7]);
        int side = u >= N;
        int v = u - side * N;
        int b = side ? bj[v] : bi[v];
        float* gm = &g_gm[side][b * H + d0];
        red_add_v4(gm,     make_float4(a[0], a[1], a[2], a[3]));
        red_add_v4(gm + 4, make_float4(a[4], a[5], a[6], a[7]));
        if (sub == 0) atomicAdd(&g_gmcnt[side][b], 1);
    } else {
        __half2 out[4];
#pragma unroll
        for (int j = 0; j < 4; j++) out[j] = __floats2half2_rn(a[2 * j], a[2 * j + 1]);
        reinterpret_cast<float4*>(g_nbh[si ^ 1])[u * 4 + sub] = *reinterpret_cast<float4*>(out);
    }
}

// ---------------- context ----------------
__global__ void k_ctx(const float* __restrict__ Wc, int B) {
    __shared__ float sW[H * H];
    for (int i = threadIdx.x; i < H * H; i += blockDim.x) sW[i] = Wc[i];
    __syncthreads();
    int g = blockIdx.x * (blockDim.x >> 5) + (threadIdx.x >> 5);
    int lane = threadIdx.x & 31;
    if (g >= 2 * B) return;
    int side = g >= B;
    int b = g - side * B;
    float mean = g_gm[side][b * H + lane] / fmaxf((float)g_gmcnt[side][b], 1.f);
    float acc = 0.f;
#pragma unroll
    for (int k = 0; k < H; k++)
        acc += __shfl_sync(0xffffffffu, mean, k) * sW[k * H + lane];
    g_ctx[side][b * H + lane] = tanhf(acc);
}

// ---------------- gated add-pool: grp-per-node, v4 RED ----------------
__global__ void k_gate(const int* __restrict__ bi, const int* __restrict__ bj, int N) {
    int gw = blockIdx.x * (blockDim.x >> 5) + (threadIdx.x >> 5);
    int lane = threadIdx.x & 31;
    int grp = lane >> 2, sub = lane & 3;
    int u = gw * 8 + grp;
    int n2 = 2 * N;
    bool alive = u < n2;
    int uc = alive ? u : (n2 - 1);
    int side = uc >= N;
    int v = uc - side * N;
    int b = side ? bj[v] : bi[v];
    int d0 = sub * 8;
    const float4* rp = reinterpret_cast<const float4*>(g_rep + uc * H + d0);
    float4 r0 = rp[0], r1 = rp[1];
    const float4* cp = reinterpret_cast<const float4*>(&g_ctx[side][b * H + d0]);
    float4 c0 = cp[0], c1 = cp[1];
    float p = r0.x * c0.x + r0.y * c0.y + r0.z * c0.z + r0.w * c0.w
            + r1.x * c1.x + r1.y * c1.y + r1.z * c1.z + r1.w * c1.w;
    p += __shfl_xor_sync(0xffffffffu, p, 1);
    p += __shfl_xor_sync(0xffffffffu, p, 2);
    if (!alive) return;
    float gate = 1.f / (1.f + expf(-p));
    float* pl = &g_pool[side][b * H + d0];
    red_add_v4(pl,     make_float4(gate * r0.x, gate * r0.y, gate * r0.z, gate * r0.w));
    red_add_v4(pl + 4, make_float4(gate * r1.x, gate * r1.y, gate * r1.z, gate * r1.w));
}

// ---------------- NTN + final MLP ----------------
__global__ void k_ntn(const float* __restrict__ Wn, const float* __restrict__ V,
                      const float* __restrict__ bn, const float* __restrict__ mw,
                      const float* __restrict__ mb, float* __restrict__ out, int B) {
    __shared__ float gk[KNTN];
    int b = blockIdx.x;
    int k = threadIdx.x >> 5;
    int lane = threadIdx.x & 31;
    float hi = g_pool[0][b * H + lane];
    float hj = g_pool[1][b * H + lane];
    float acc = 0.f;
    const float* W = Wn + k * H * H;
#pragma unroll
    for (int i = 0; i < H; i++)
        acc += __shfl_sync(0xffffffffu, hi, i) * W[i * H + lane];
    float p = acc * hj + V[k * 2 * H + lane] * hi + V[k * 2 * H + H + lane] * hj;
#pragma unroll
    for (int o = 16; o > 0; o >>= 1) p += __shfl_xor_sync(0xffffffffu, p, o);
    if (lane == 0) gk[k] = p + bn[k];
    __syncthreads();
    if (k == 0) {
        float v = gk[lane] * mw[lane];
#pragma unroll
        for (int o = 16; o > 0; o >>= 1) v += __shfl_xor_sync(0xffffffffu, v, o);
        if (lane == 0) out[b] = v + mb[0];
    }
}

extern "C" void kernel_launch(void* const* d_in, const int* in_sizes, int n_in,
                              void* d_out, int out_size) {
    const float* x_i   = (const float*)d_in[0];
    const int*   ei_i  = (const int*)d_in[1];
    const int*   bat_i = (const int*)d_in[2];
    const float* x_j   = (const float*)d_in[3];
    const int*   ei_j  = (const int*)d_in[4];
    const int*   bat_j = (const int*)d_in[5];
    const float* W_gcn = (const float*)d_in[6];
    const float* b_gcn = (const float*)d_in[7];
    const float* sage_lin_l = (const float*)d_in[8];
    const float* sage_b_l   = (const float*)d_in[9];
    const float* sage_lin_r = (const float*)d_in[10];
    const float* weight_c   = (const float*)d_in[11];
    const float* W_ntn      = (const float*)d_in[12];
    const float* V_ntn      = (const float*)d_in[13];
    const float* b_ntn      = (const float*)d_in[14];
    const float* mlp_w      = (const float*)d_in[15];
    const float* mlp_b      = (const float*)d_in[16];

    int N = in_sizes[0] / FIN;
    int E = in_sizes[1] / 2;
    int B = out_size;
    float* out = (float*)d_out;

    const int TB = 256;
    int n2 = 2 * N;
    int gridN2  = (n2 + TB - 1) / TB;
    int gridF   = (2 * E + TB - 1) / TB;        // 1 edge/thread
    int gridWN2 = (n2 + 7) / 8;                 // warp-per-node (xw)
    int gridG   = (n2 + 63) / 64;               // grp-per-node (8 nodes/warp)
    int gridWB2 = (2 * B + 7) / 8;

    k_init_cur<<<gridN2, TB>>>(n2);
    k_init_gm<<<(B * H + TB - 1) / TB, TB>>>(B);
    k_init_cnt<<<(B + TB - 1) / TB, TB>>>(B);
    k_fill<<<gridF, TB>>>(ei_i, ei_j, N, E);
    k_xw<<<gridWN2, TB>>>(x_i, x_j, W_gcn, N);

    k_gcn<<<gridG, TB>>>(b_gcn, N);                                         // nbh0 -> nbh1 (h1)
    // SAGE layer 0: lin (h1 in nbh1 -> z in nbh0, r in rh), pure gather -> h2 in nbh1
    k_lin<<<gridG, TB>>>(1, sage_lin_l, sage_b_l, sage_lin_r, N);
    k_pure<<<gridG, TB>>>(0, N, 0, bat_i, bat_j);
    // SAGE layer 1: lin (h2 in nbh1 -> z2 in nbh0, r2 in rh), pure gather -> rep (+pool)
    k_lin<<<gridG, TB>>>(1, sage_lin_l + H * H, sage_b_l + H, sage_lin_r + H * H, N);
    k_pure<<<gridG, TB>>>(0, N, 1, bat_i, bat_j);

    k_ctx<<<gridWB2, TB>>>(weight_c, B);
    k_gate<<<gridG, TB>>>(bat_i, bat_j, N);
    k_ntn<<<B, 1024>>>(W_ntn, V_ntn, b_ntn, mlp_w, mlp_b, out, B);
}

// round 17
// speedup vs baseline: 1.3845x; 1.3845x over previous
#include <cuda_runtime.h>
#include <cuda_fp16.h>
#include <math.h>

#define NMAX 100000
#define EMAX 3200000
#define BMAX 512
#define H 32
#define FIN 64
#define KNTN 32
#define BUCKET 64

typedef unsigned long long ull;

// ---- static scratch (no allocation) ----
__device__ __align__(16) __half g_nbh[2][2 * NMAX * H];   // fp16 feature ping-pong
__device__ __align__(16) float  g_rep[2 * NMAX * H];      // final rep (fp32)
__device__ int   g_cur[2 * NMAX];                         // degree / bucket cursor
__device__ int   g_csr[2 * NMAX * BUCKET + 1024];         // interleaved CSR (+pad for prefetch)
__device__ float g_gm[2][BMAX * H];
__device__ int   g_gmcnt[2][BMAX];
__device__ float g_pool[2][BMAX * H];
__device__ float g_ctx[2][BMAX * H];

// ---- f32x2 packed helpers ----
__device__ __forceinline__ ull pack2(float a, float b) {
    ull r; asm("mov.b64 %0, {%1,%2};" : "=l"(r) : "f"(a), "f"(b)); return r;
}
__device__ __forceinline__ void unpack2(ull v, float& a, float& b) {
    asm("mov.b64 {%0,%1}, %2;" : "=f"(a), "=f"(b) : "l"(v));
}
__device__ __forceinline__ ull fma2(ull a, ull b, ull c) {
    ull d; asm("fma.rn.f32x2 %0, %1, %2, %3;" : "=l"(d) : "l"(a), "l"(b), "l"(c));
    return d;
}
__device__ __forceinline__ void red_add_v4(float* p, float4 v) {
    asm volatile("red.global.add.v4.f32 [%0], {%1,%2,%3,%4};"
                 :: "l"(p), "f"(v.x), "f"(v.y), "f"(v.z), "f"(v.w) : "memory");
}

// interleaved CSR slot for node u, entry t
__device__ __forceinline__ int csr_slot(int u, int t) {
    return (u & ~7) * BUCKET + t * 8 + (u & 7);
}

// ---------------- init (split 3-way so fill is launch #4 for ncu) ----------------
__global__ void k_init_cur(int n2) {
    int i = blockIdx.x * blockDim.x + threadIdx.x;
    if (i < n2) g_cur[i] = 0;
}
__global__ void k_init_gm(int B) {
    int i = blockIdx.x * blockDim.x + threadIdx.x;
    if (i < B * H) {
        g_gm[0][i] = 0.f; g_gm[1][i] = 0.f;
        g_pool[0][i] = 0.f; g_pool[1][i] = 0.f;
    }
}
__global__ void k_init_cnt(int B) {
    int i = blockIdx.x * blockDim.x + threadIdx.x;
    if (i < B) { g_gmcnt[0][i] = 0; g_gmcnt[1][i] = 0; }
}

// ---------------- CSR fill: 1 edge/thread (proven 84us) ----------------
__global__ void k_fill(const int* __restrict__ ei, const int* __restrict__ ej,
                       int N, int E) {
    int idx = blockIdx.x * blockDim.x + threadIdx.x;
    if (idx >= 2 * E) return;
    int side = idx >= E;
    int e = idx - side * E;
    const int* el = side ? ej : ei;
    int s = el[e];
    int d = el[E + e];
    int u = side * N + d;
    int pos = atomicAdd(&g_cur[u], 1);
    if (pos < BUCKET) g_csr[csr_slot(u, pos)] = side * N + s;
}

// ---------------- xw: y = (x @ W_gcn) * dinv -> nbh[0] (fp16, prescaled) ----------------
__global__ void k_xw(const float* __restrict__ xi, const float* __restrict__ xj,
                     const float* __restrict__ W, int N) {
    __shared__ float2 sW2[32 * H];
    for (int i = threadIdx.x; i < 32 * H; i += blockDim.x)
        sW2[i] = make_float2(W[i], W[i + 32 * H]);
    __syncthreads();
    int u = blockIdx.x * (blockDim.x >> 5) + (threadIdx.x >> 5);
    int lane = threadIdx.x & 31;
    if (u >= 2 * N) return;
    int side = u >= N;
    int v = u - side * N;
    const float* x = side ? xj : xi;
    float xa = x[v * FIN + lane];
    float xb = x[v * FIN + 32 + lane];
    ull acc2 = pack2(0.f, 0.f);
    const ull* w2 = reinterpret_cast<const ull*>(sW2);
#pragma unroll
    for (int k = 0; k < 32; k++) {
        float ak = __shfl_sync(0xffffffffu, xa, k);
        float bk = __shfl_sync(0xffffffffu, xb, k);
        acc2 = fma2(pack2(ak, bk), w2[k * H + lane], acc2);
    }
    float lo, hi;
    unpack2(acc2, lo, hi);
    float dinv = rsqrtf((float)g_cur[u] + 1.f);
    g_nbh[0][u * H + lane] = __float2half((lo + hi) * dinv);
}

// ---- grp gather, unroll 2, software-pipelined index prefetch ----
__device__ __forceinline__ void grp_gather(__half2* acc, const float4* rows,
                                           int u, int deg, int sub) {
    const int* idx = g_csr + (u & ~7) * BUCKET + (u & 7);
    __half2 a1[4];
#pragma unroll
    for (int j = 0; j < 4; j++) { acc[j] = __float2half2_rn(0.f); a1[j] = acc[j]; }
    int s0 = idx[0];
    int s1 = idx[8];
    int t = 0;
    for (; t + 2 <= deg; t += 2) {
        float4 v0 = rows[s0 * 4 + sub];
        float4 v1 = rows[s1 * 4 + sub];
        s0 = idx[(t + 2) * 8];
        s1 = idx[(t + 2) * 8 + 8];
        const __half2* p0 = reinterpret_cast<const __half2*>(&v0);
        const __half2* p1 = reinterpret_cast<const __half2*>(&v1);
#pragma unroll
        for (int j = 0; j < 4; j++) acc[j] = __hadd2(acc[j], p0[j]);
#pragma unroll
        for (int j = 0; j < 4; j++) a1[j] = __hadd2(a1[j], p1[j]);
    }
    if (t < deg) {
        float4 v = rows[s0 * 4 + sub];
        const __half2* p = reinterpret_cast<const __half2*>(&v);
#pragma unroll
        for (int j = 0; j < 4; j++) acc[j] = __hadd2(acc[j], p[j]);
    }
#pragma unroll
    for (int j = 0; j < 4; j++) acc[j] = __hadd2(acc[j], a1[j]);
}

// ---------------- fused GCN gather + finalize: nbh0(prescaled) -> nbh1 ----------------
__global__ void k_gcn(const float* __restrict__ bg, int N) {
    int gw = blockIdx.x * (blockDim.x >> 5) + (threadIdx.x >> 5);
    int lane = threadIdx.x & 31;
    int grp = lane >> 2, sub = lane & 3;
    int u = gw * 8 + grp;
    if (u >= 2 * N) return;
    int deg = min(g_cur[u], BUCKET);
    const float4* y4 = reinterpret_cast<const float4*>(g_nbh[0]);
    __half2 acc[4];
    grp_gather(acc, y4, u, deg, sub);
    float4 v = y4[u * 4 + sub];
    const __half2* p = reinterpret_cast<const __half2*>(&v);
    float dinv = rsqrtf((float)g_cur[u] + 1.f);
    const float4* b4 = reinterpret_cast<const float4*>(bg);
    float4 b0 = b4[sub * 2], b1 = b4[sub * 2 + 1];
    float bv[8] = {b0.x, b0.y, b0.z, b0.w, b1.x, b1.y, b1.z, b1.w};
    __half2 out[4];
#pragma unroll
    for (int j = 0; j < 4; j++) {
        float2 s = __half22float2(acc[j]);
        float2 f = __half22float2(p[j]);
        float a = fmaxf((s.x + f.x) * dinv + bv[2 * j], 0.f);
        float b = fmaxf((s.y + f.y) * dinv + bv[2 * j + 1], 0.f);
        out[j] = __floats2half2_rn(a, b);
    }
    reinterpret_cast<float4*>(g_nbh[1])[u * 4 + sub] = *reinterpret_cast<float4*>(out);
}

// ---------------- fused SAGE gather + half2-weight GEMV ----------------
// Weights in smem as half2 {Wl[k][d], Wr[k][d]} (4KB total). Per k:
// 1 packed shfl broadcast of {m,h} + 2 LDS.128 + 8 HFMA2. LDS bytes halved vs R13.
__global__ void k_sage(int si,
                       const float* __restrict__ Wl, const float* __restrict__ bl,
                       const float* __restrict__ Wr, int N,
                       int do_pool, const int* __restrict__ bi, const int* __restrict__ bj) {
    __shared__ __half2 sW[H * H];   // {Wl[k][d], Wr[k][d]}
    for (int i = threadIdx.x; i < H * H; i += blockDim.x)
        sW[i] = __floats2half2_rn(Wl[i], Wr[i]);
    __syncthreads();
    int gw = blockIdx.x * (blockDim.x >> 5) + (threadIdx.x >> 5);
    int lane = threadIdx.x & 31;
    int grp = lane >> 2, sub = lane & 3;
    int n2 = 2 * N;
    int u = gw * 8 + grp;
    bool alive = u < n2;
    int uc = alive ? u : (n2 - 1);
    int deg = min(g_cur[uc], BUCKET);
    int degl = alive ? deg : 0;
    const float4* h4 = reinterpret_cast<const float4*>(g_nbh[si]);
    __half2 acc[4];
    grp_gather(acc, h4, uc, degl, sub);
    // mh[j] = packed {m[j], hv[j]} for this lane's 8 dims
    float invc = 1.f / fmaxf((float)deg, 1.f);
    unsigned int mhu[8];
    {
        float4 v = h4[uc * 4 + sub];
        const __half2* p = reinterpret_cast<const __half2*>(&v);
#pragma unroll
        for (int j = 0; j < 4; j++) {
            float2 s = __half22float2(acc[j]);
            float2 f = __half22float2(p[j]);
            __half2 t0 = __floats2half2_rn(s.x * invc, f.x);
            __half2 t1 = __floats2half2_rn(s.y * invc, f.y);
            mhu[2 * j]     = *reinterpret_cast<unsigned int*>(&t0);
            mhu[2 * j + 1] = *reinterpret_cast<unsigned int*>(&t1);
        }
    }
    int d0 = sub * 8;
    // acch[j] accumulates {sum m*Wl, sum h*Wr} for dim d0+j
    __half2 acch[8];
#pragma unroll
    for (int j = 0; j < 8; j++) acch[j] = __float2half2_rn(0.f);
    int lanebase = lane & ~3;
    for (int k0 = 0; k0 < 32; k0 += 8) {
        int srcl = lanebase | (k0 >> 3);
#pragma unroll
        for (int i = 0; i < 8; i++) {
            int k = k0 + i;
            unsigned int bu = __shfl_sync(0xffffffffu, mhu[i], srcl);
            __half2 b2 = *reinterpret_cast<__half2*>(&bu);
            const float4* w4 = reinterpret_cast<const float4*>(sW + k * H + d0);
            float4 wa = w4[0], wb = w4[1];
            const __half2* pa = reinterpret_cast<const __half2*>(&wa);
            const __half2* pb = reinterpret_cast<const __half2*>(&wb);
            acch[0] = __hfma2(b2, pa[0], acch[0]);
            acch[1] = __hfma2(b2, pa[1], acch[1]);
            acch[2] = __hfma2(b2, pa[2], acch[2]);
            acch[3] = __hfma2(b2, pa[3], acch[3]);
            acch[4] = __hfma2(b2, pb[0], acch[4]);
            acch[5] = __hfma2(b2, pb[1], acch[5]);
            acch[6] = __hfma2(b2, pb[2], acch[6]);
            acch[7] = __hfma2(b2, pb[3], acch[7]);
        }
    }
    // fp32 epilogue: a[j] = relu(lo+hi + bias)
    const float4* bl4 = reinterpret_cast<const float4*>(bl + d0);
    float4 bb0 = bl4[0], bb1 = bl4[1];
    float bv[8] = {bb0.x, bb0.y, bb0.z, bb0.w, bb1.x, bb1.y, bb1.z, bb1.w};
    float a[8];
#pragma unroll
    for (int j = 0; j < 8; j++) {
        float2 f = __half22float2(acch[j]);
        a[j] = fmaxf(f.x + f.y + bv[j], 0.f);
    }
    if (!alive) return;
    if (do_pool) {
        float4* rp = reinterpret_cast<float4*>(g_rep + u * H + d0);
        rp[0] = make_float4(a[0], a[1], a[2], a[3]);
        rp[1] = make_float4(a[4], a[5], a[6], a[7]);
        int side = u >= N;
        int v = u - side * N;
        int b = side ? bj[v] : bi[v];
        float* gm = &g_gm[side][b * H + d0];
        red_add_v4(gm,     make_float4(a[0], a[1], a[2], a[3]));
        red_add_v4(gm + 4, make_float4(a[4], a[5], a[6], a[7]));
        if (sub == 0) atomicAdd(&g_gmcnt[side][b], 1);
    } else {
        __half2 out[4];
#pragma unroll
        for (int j = 0; j < 4; j++) out[j] = __floats2half2_rn(a[2 * j], a[2 * j + 1]);
        reinterpret_cast<float4*>(g_nbh[si ^ 1])[u * 4 + sub] = *reinterpret_cast<float4*>(out);
    }
}

// ---------------- context ----------------
__global__ void k_ctx(const float* __restrict__ Wc, int B) {
    __shared__ float sW[H * H];
    for (int i = threadIdx.x; i < H * H; i += blockDim.x) sW[i] = Wc[i];
    __syncthreads();
    int g = blockIdx.x * (blockDim.x >> 5) + (threadIdx.x >> 5);
    int lane = threadIdx.x & 31;
    if (g >= 2 * B) return;
    int side = g >= B;
    int b = g - side * B;
    float mean = g_gm[side][b * H + lane] / fmaxf((float)g_gmcnt[side][b], 1.f);
    float acc = 0.f;
#pragma unroll
    for (int k = 0; k < H; k++)
        acc += __shfl_sync(0xffffffffu, mean, k) * sW[k * H + lane];
    g_ctx[side][b * H + lane] = tanhf(acc);
}

// ---------------- gated add-pool: grp-per-node, v4 RED ----------------
__global__ void k_gate(const int* __restrict__ bi, const int* __restrict__ bj, int N) {
    int gw = blockIdx.x * (blockDim.x >> 5) + (threadIdx.x >> 5);
    int lane = threadIdx.x & 31;
    int grp = lane >> 2, sub = lane & 3;
    int u = gw * 8 + grp;
    int n2 = 2 * N;
    bool alive = u < n2;
    int uc = alive ? u : (n2 - 1);
    int side = uc >= N;
    int v = uc - side * N;
    int b = side ? bj[v] : bi[v];
    int d0 = sub * 8;
    const float4* rp = reinterpret_cast<const float4*>(g_rep + uc * H + d0);
    float4 r0 = rp[0], r1 = rp[1];
    const float4* cp = reinterpret_cast<const float4*>(&g_ctx[side][b * H + d0]);
    float4 c0 = cp[0], c1 = cp[1];
    float p = r0.x * c0.x + r0.y * c0.y + r0.z * c0.z + r0.w * c0.w
            + r1.x * c1.x + r1.y * c1.y + r1.z * c1.z + r1.w * c1.w;
    p += __shfl_xor_sync(0xffffffffu, p, 1);
    p += __shfl_xor_sync(0xffffffffu, p, 2);
    if (!alive) return;
    float gate = 1.f / (1.f + expf(-p));
    float* pl = &g_pool[side][b * H + d0];
    red_add_v4(pl,     make_float4(gate * r0.x, gate * r0.y, gate * r0.z, gate * r0.w));
    red_add_v4(pl + 4, make_float4(gate * r1.x, gate * r1.y, gate * r1.z, gate * r1.w));
}

// ---------------- NTN + final MLP ----------------
__global__ void k_ntn(const float* __restrict__ Wn, const float* __restrict__ V,
                      const float* __restrict__ bn, const float* __restrict__ mw,
                      const float* __restrict__ mb, float* __restrict__ out, int B) {
    __shared__ float gk[KNTN];
    int b = blockIdx.x;
    int k = threadIdx.x >> 5;
    int lane = threadIdx.x & 31;
    float hi = g_pool[0][b * H + lane];
    float hj = g_pool[1][b * H + lane];
    float acc = 0.f;
    const float* W = Wn + k * H * H;
#pragma unroll
    for (int i = 0; i < H; i++)
        acc += __shfl_sync(0xffffffffu, hi, i) * W[i * H + lane];
    float p = acc * hj + V[k * 2 * H + lane] * hi + V[k * 2 * H + H + lane] * hj;
#pragma unroll
    for (int o = 16; o > 0; o >>= 1) p += __shfl_xor_sync(0xffffffffu, p, o);
    if (lane == 0) gk[k] = p + bn[k];
    __syncthreads();
    if (k == 0) {
        float v = gk[lane] * mw[lane];
#pragma unroll
        for (int o = 16; o > 0; o >>= 1) v += __shfl_xor_sync(0xffffffffu, v, o);
        if (lane == 0) out[b] = v + mb[0];
    }
}

extern "C" void kernel_launch(void* const* d_in, const int* in_sizes, int n_in,
                              void* d_out, int out_size) {
    const float* x_i   = (const float*)d_in[0];
    const int*   ei_i  = (const int*)d_in[1];
    const int*   bat_i = (const int*)d_in[2];
    const float* x_j   = (const float*)d_in[3];
    const int*   ei_j  = (const int*)d_in[4];
    const int*   bat_j = (const int*)d_in[5];
    const float* W_gcn = (const float*)d_in[6];
    const float* b_gcn = (const float*)d_in[7];
    const float* sage_lin_l = (const float*)d_in[8];
    const float* sage_b_l   = (const float*)d_in[9];
    const float* sage_lin_r = (const float*)d_in[10];
    const float* weight_c   = (const float*)d_in[11];
    const float* W_ntn      = (const float*)d_in[12];
    const float* V_ntn      = (const float*)d_in[13];
    const float* b_ntn      = (const float*)d_in[14];
    const float* mlp_w      = (const float*)d_in[15];
    const float* mlp_b      = (const float*)d_in[16];

    int N = in_sizes[0] / FIN;
    int E = in_sizes[1] / 2;
    int B = out_size;
    float* out = (float*)d_out;

    const int TB = 256;
    int n2 = 2 * N;
    int gridN2  = (n2 + TB - 1) / TB;
    int gridF   = (2 * E + TB - 1) / TB;        // 1 edge/thread
    int gridWN2 = (n2 + 7) / 8;                 // warp-per-node (xw)
    int gridG   = (n2 + 63) / 64;               // grp-per-node (8 nodes/warp)
    int gridWB2 = (2 * B + 7) / 8;

    k_init_cur<<<gridN2, TB>>>(n2);
    k_init_gm<<<(B * H + TB - 1) / TB, TB>>>(B);
    k_init_cnt<<<(B + TB - 1) / TB, TB>>>(B);
    k_fill<<<gridF, TB>>>(ei_i, ei_j, N, E);
    k_xw<<<gridWN2, TB>>>(x_i, x_j, W_gcn, N);

    k_gcn<<<gridG, TB>>>(b_gcn, N);                                         // nbh0 -> nbh1
    k_sage<<<gridG, TB>>>(1, sage_lin_l, sage_b_l, sage_lin_r,
                          N, 0, bat_i, bat_j);                              // nbh1 -> nbh0
    k_sage<<<gridG, TB>>>(0, sage_lin_l + H * H, sage_b_l + H,
                          sage_lin_r + H * H, N, 1, bat_i, bat_j);          // nbh0 -> rep (+pool)

    k_ctx<<<gridWB2, TB>>>(weight_c, B);
    k_gate<<<gridG, TB>>>(bat_i, bat_j, N);
    k_ntn<<<B, 1024>>>(W_ntn, V_ntn, b_ntn, mlp_w, mlp_b, out, B);
}